// round 16
// baseline (speedup 1.0000x reference)
#include <cuda_runtime.h>
#include <cuda_fp16.h>
#include <stdint.h>
#include <math.h>

#define NN 50000
#define NN2 50048          // padded to multiple of 64 for gemm2 tiles
#define FE 800000
#define ET (FE + NN)
#define NPART 196          // ceil(NN/256)
#define CH2 256
#define FULLM 0xffffffffu

// ---------------- scratch ----------------------------------------------------
__device__ __half2 g_o1h[NN2 * 128];   // elu(layer1 out) fp16 (gemm2 A)
__device__ float   g_as1[NN * 4];
__device__ float   g_ad1[NN * 4];
__device__ __half  g_W2h[64 * 256];    // W2 fp16
__device__ __half2 g_h2h[NN2 * 32];    // layer2 pre-agg features fp16
__device__ float   g_as2[NN];
__device__ float   g_ad2[NN];
__device__ int     g_eid[ET];
__device__ int     g_cnt[NN];          // BSS-zero at load; re-zeroed by k_fagg1g each call
__device__ int     g_off[NN + 1];
__device__ int     g_cur[NN];
__device__ int     g_is64;
__device__ float   g_ws1s[64];
__device__ float   g_ws1d[64];
__device__ float   g_v2s[256];
__device__ float   g_v2d[256];

__device__ __forceinline__ float lrelu(float v) { return v > 0.f ? v : 0.2f * v; }
__device__ __forceinline__ float elu(float v)   { return v > 0.f ? v : expm1f(v); }
__device__ __forceinline__ uint32_t su32(const void* p) {
    return (uint32_t)__cvta_generic_to_shared(p);
}
#define NEG_INF __int_as_float(0xff800000)

// ---------------- init: dtype detect (block 0) + weight folds (block 1) ----------
__global__ void k_init2(const int* __restrict__ ei32,
                        const float* __restrict__ W1,
                        const float* __restrict__ as1, const float* __restrict__ ad1,
                        const float* __restrict__ W2,
                        const float* __restrict__ as2, const float* __restrict__ ad2) {
    int t = threadIdx.x;
    if (blockIdx.x == 0) {
        int nz = 0;
        for (int k = t; k < 1024; k += 256) nz |= ei32[2 * k + 1];
        int any = __syncthreads_or(nz);
        if (t == 0) g_is64 = (any == 0);
    } else {
        if (t < 64) {
            int h = t >> 4, ii = t & 15;
            float s = 0.f, d = 0.f;
            for (int c = 0; c < 64; c++) {
                float w = W1[(h * 64 + c) * 16 + ii];
                s += as1[h * 64 + c] * w;
                d += ad1[h * 64 + c] * w;
            }
            g_ws1s[t] = s; g_ws1d[t] = d;
        }
        {
            float s = 0.f, d = 0.f;
            for (int o = 0; o < 64; o++) {
                float w = W2[o * 256 + t];
                s += as2[o] * w;
                d += ad2[o] * w;
            }
            g_v2s[t] = s; g_v2d[t] = d;
        }
        for (int j = 0; j < 64; j++) {
            int idx = j * 256 + t;
            g_W2h[idx] = __float2half(W2[idx]);
        }
    }
}

// ---------------- pre: layer-1 logits from x + edge in-degree counting -----------
__global__ void k_pre(const float* __restrict__ x, const int* __restrict__ ei32) {
    __shared__ float ws[64], wd[64];
    int t = threadIdx.x;
    if (t < 64) { ws[t] = g_ws1s[t]; wd[t] = g_ws1d[t]; }
    __syncthreads();
    int i = blockIdx.x * 256 + t;
    if (i < ET) {
        int d;
        if (i < FE) d = g_is64 ? ei32[2 * (FE + i)] : ei32[FE + i];
        else        d = i - FE;
        atomicAdd(&g_cnt[d], 1);
    }
    if (i < NN) {
        const float4* xv = reinterpret_cast<const float4*>(x + i * 16);
        float4 x0 = xv[0], x1 = xv[1], x2 = xv[2], x3 = xv[3];
        float4 av, bv;
        float* ap = (float*)&av;
        float* bp = (float*)&bv;
#pragma unroll
        for (int h = 0; h < 4; h++) {
            const float* s = ws + h * 16;
            const float* d = wd + h * 16;
            ap[h] = x0.x * s[0] + x0.y * s[1] + x0.z * s[2] + x0.w * s[3]
                  + x1.x * s[4] + x1.y * s[5] + x1.z * s[6] + x1.w * s[7]
                  + x2.x * s[8] + x2.y * s[9] + x2.z * s[10] + x2.w * s[11]
                  + x3.x * s[12] + x3.y * s[13] + x3.z * s[14] + x3.w * s[15];
            bp[h] = x0.x * d[0] + x0.y * d[1] + x0.z * d[2] + x0.w * d[3]
                  + x1.x * d[4] + x1.y * d[5] + x1.z * d[6] + x1.w * d[7]
                  + x2.x * d[8] + x2.y * d[9] + x2.z * d[10] + x2.w * d[11]
                  + x3.x * d[12] + x3.y * d[13] + x3.z * d[14] + x3.w * d[15];
        }
        *reinterpret_cast<float4*>(&g_as1[i * 4]) = av;
        *reinterpret_cast<float4*>(&g_ad1[i * 4]) = bv;
    }
}

// ---------------- fused scan: redundant chunk partials + own-chunk offsets --------
__global__ void k_scanF() {
    __shared__ int sp[256];
    __shared__ int sm[256];
    int b = blockIdx.x, t = threadIdx.x, i = b * 256 + t;
    // thread t computes the partial sum of chunk t (196 chunks of 256 counts)
    int part = 0;
    if (t < NPART) {
        const int4* c4 = reinterpret_cast<const int4*>(g_cnt) + t * 64;
        int base4 = t * 64;
#pragma unroll 4
        for (int j = 0; j < 64; j++) {
            if ((base4 + j) * 4 < NN) {
                int4 v = c4[j];
                part += v.x + v.y + v.z + v.w;
            }
        }
    }
    sp[t] = part;
    int v = (i < NN) ? g_cnt[i] : 0;
    sm[t] = v;
    __syncthreads();
#pragma unroll
    for (int s = 1; s < 256; s <<= 1) {
        int a = (t >= s) ? sp[t - s] : 0;
        int c = (t >= s) ? sm[t - s] : 0;
        __syncthreads();
        sp[t] += a; sm[t] += c;
        __syncthreads();
    }
    int base = (b > 0) ? sp[b - 1] : 0;      // exclusive prefix over chunk partials
    if (i < NN) {
        int off = base + sm[t] - v;
        g_off[i] = off; g_cur[i] = off;
    }
    if (b == 0 && t == 0) g_off[NN] = ET;
}
__global__ void k_scatter(const int* __restrict__ ei32) {
    int i = blockIdx.x * blockDim.x + threadIdx.x;
    if (i >= ET) return;
    int s, d;
    if (i < FE) {
        if (g_is64) { s = ei32[2 * i]; d = ei32[2 * (FE + i)]; }
        else        { s = ei32[i];     d = ei32[FE + i]; }
    } else { s = i - FE; d = s; }
    int pos = atomicAdd(&g_cur[d], 1);
    g_eid[pos] = s;
}

// ---------------- layer 1 FUSED: x-aggregation (linearity) + GEMM + ELU -----------
// Phase A (warp per dst, 8 dst/block): xagg[d][h][:] = softmax-weighted sum of x rows,
//   staged in SMEM. Phase B: out1 = xagg @ W1^T + b1 -> ELU -> fp16 o1h.
// Also re-zeroes g_cnt[d] for the next call (graph replay determinism).
__global__ void k_fagg1g(const float* __restrict__ x,
                         const float* __restrict__ W1, const float* __restrict__ b1) {
    __shared__ float xs[8 * 64];
    int t = threadIdx.x;
    int wid = t >> 5, lane = t & 31;
    int b = blockIdx.x;
    int d = b * 8 + wid;
    {
        int beg = g_off[d], end = g_off[d + 1];
        if (lane == 0) g_cnt[d] = 0;    // reset for next launch
        float4 adv = *reinterpret_cast<const float4*>(&g_ad1[d * 4]);
        int c = lane & 15, half = lane >> 4;
        float gm0 = NEG_INF, gm1 = NEG_INF, gm2 = NEG_INF, gm3 = NEG_INF;
        float gs0 = 0.f, gs1 = 0.f, gs2 = 0.f, gs3 = 0.f;
        float a0 = 0.f, a1 = 0.f, a2 = 0.f, a3 = 0.f;
        for (int cb = beg; cb < end; cb += 32) {
            int cnt = min(end - cb, 32);
            int s = 0;
            float l0 = NEG_INF, l1 = NEG_INF, l2 = NEG_INF, l3 = NEG_INF;
            if (lane < cnt) {
                s = g_eid[cb + lane];
                float4 as = *reinterpret_cast<const float4*>(&g_as1[s * 4]);
                l0 = lrelu(as.x + adv.x); l1 = lrelu(as.y + adv.y);
                l2 = lrelu(as.z + adv.z); l3 = lrelu(as.w + adv.w);
            }
            float m0 = l0, m1 = l1, m2 = l2, m3 = l3;
#pragma unroll
            for (int o = 16; o > 0; o >>= 1) {
                m0 = fmaxf(m0, __shfl_xor_sync(FULLM, m0, o));
                m1 = fmaxf(m1, __shfl_xor_sync(FULLM, m1, o));
                m2 = fmaxf(m2, __shfl_xor_sync(FULLM, m2, o));
                m3 = fmaxf(m3, __shfl_xor_sync(FULLM, m3, o));
            }
            float w0 = (lane < cnt) ? __expf(l0 - m0) : 0.f;
            float w1 = (lane < cnt) ? __expf(l1 - m1) : 0.f;
            float w2 = (lane < cnt) ? __expf(l2 - m2) : 0.f;
            float w3 = (lane < cnt) ? __expf(l3 - m3) : 0.f;
            float s0 = w0, s1 = w1, s2 = w2, s3 = w3;
#pragma unroll
            for (int o = 16; o > 0; o >>= 1) {
                s0 += __shfl_xor_sync(FULLM, s0, o);
                s1 += __shfl_xor_sync(FULLM, s1, o);
                s2 += __shfl_xor_sync(FULLM, s2, o);
                s3 += __shfl_xor_sync(FULLM, s3, o);
            }
            float c0 = 0.f, c1 = 0.f, c2 = 0.f, c3 = 0.f;
            for (int eb = 0; eb < cnt; eb += 2) {
                int e = (eb + half) & 31;
                float we0 = __shfl_sync(FULLM, w0, e);
                float we1 = __shfl_sync(FULLM, w1, e);
                float we2 = __shfl_sync(FULLM, w2, e);
                float we3 = __shfl_sync(FULLM, w3, e);
                int   se  = __shfl_sync(FULLM, s,  e);
                if (eb + half < cnt) {
                    float xv = x[se * 16 + c];
                    c0 += we0 * xv; c1 += we1 * xv;
                    c2 += we2 * xv; c3 += we3 * xv;
                }
            }
            float nm0 = fmaxf(gm0, m0), nm1 = fmaxf(gm1, m1);
            float nm2 = fmaxf(gm2, m2), nm3 = fmaxf(gm3, m3);
            float f0 = __expf(gm0 - nm0), q0 = __expf(m0 - nm0);
            float f1 = __expf(gm1 - nm1), q1 = __expf(m1 - nm1);
            float f2 = __expf(gm2 - nm2), q2 = __expf(m2 - nm2);
            float f3 = __expf(gm3 - nm3), q3 = __expf(m3 - nm3);
            gs0 = gs0 * f0 + s0 * q0;  a0 = a0 * f0 + c0 * q0;  gm0 = nm0;
            gs1 = gs1 * f1 + s1 * q1;  a1 = a1 * f1 + c1 * q1;  gm1 = nm1;
            gs2 = gs2 * f2 + s2 * q2;  a2 = a2 * f2 + c2 * q2;  gm2 = nm2;
            gs3 = gs3 * f3 + s3 * q3;  a3 = a3 * f3 + c3 * q3;  gm3 = nm3;
        }
        a0 += __shfl_down_sync(FULLM, a0, 16);
        a1 += __shfl_down_sync(FULLM, a1, 16);
        a2 += __shfl_down_sync(FULLM, a2, 16);
        a3 += __shfl_down_sync(FULLM, a3, 16);
        if (lane < 16) {
            float* o = xs + wid * 64;
            o[c]      = a0 / (gs0 + 1e-16f);
            o[16 + c] = a1 / (gs1 + 1e-16f);
            o[32 + c] = a2 / (gs2 + 1e-16f);
            o[48 + c] = a3 / (gs3 + 1e-16f);
        }
    }
    __syncthreads();
    // ---- phase B: out1 = xagg @ W1^T + b1 -> ELU -> fp16 ----
    const float4* W4 = reinterpret_cast<const float4*>(W1) + t * 4;
    float4 w0 = W4[0], w1 = W4[1], w2 = W4[2], w3 = W4[3];
    float bb = b1[t];
    int h16 = (t >> 6) * 16;
#pragma unroll
    for (int j = 0; j < 8; j++) {
        const float* xv = xs + j * 64 + h16;
        float acc = xv[0] * w0.x + xv[1] * w0.y + xv[2] * w0.z + xv[3] * w0.w
                  + xv[4] * w1.x + xv[5] * w1.y + xv[6] * w1.z + xv[7] * w1.w
                  + xv[8] * w2.x + xv[9] * w2.y + xv[10] * w2.z + xv[11] * w2.w
                  + xv[12] * w3.x + xv[13] * w3.y + xv[14] * w3.z + xv[15] * w3.w;
        acc = elu(acc + bb);
        float hi = __shfl_down_sync(FULLM, acc, 1);
        if (!(t & 1)) g_o1h[(b * 8 + j) * 128 + (t >> 1)] = __floats2half2_rn(acc, hi);
    }
}

// ---------------- layer 2 GEMM (tensor cores) + fused alpha2 epilogue -------------
#define MMA16816(C, A0, A1, A2, A3, B0, B1)                                   \
    asm volatile("mma.sync.aligned.m16n8k16.row.col.f32.f16.f16.f32 "          \
        "{%0,%1,%2,%3}, {%4,%5,%6,%7}, {%8,%9}, {%0,%1,%2,%3};"                \
        : "+f"(C[0]), "+f"(C[1]), "+f"(C[2]), "+f"(C[3])                       \
        : "r"(A0), "r"(A1), "r"(A2), "r"(A3), "r"(B0), "r"(B1))

__global__ void k_gemm2() {
    __shared__ __align__(16) __half sA[64 * 256];
    __shared__ __align__(16) __half sW[64 * 256];
    __shared__ float svs[256], svd[256];
    int t = threadIdx.x;               // 128
    int base = blockIdx.x * 64;
    const uint4* gA = reinterpret_cast<const uint4*>(g_o1h) + base * 32;
    const uint4* gW = reinterpret_cast<const uint4*>(g_W2h);
    svs[t] = g_v2s[t]; svs[t + 128] = g_v2s[t + 128];
    svd[t] = g_v2d[t]; svd[t + 128] = g_v2d[t + 128];
#pragma unroll
    for (int j = 0; j < 16; j++) {
        int i = j * 128 + t;
        int r = i >> 5, c = i & 31;
        int sc = c ^ (r & 7);
        *reinterpret_cast<uint4*>(&sA[r * 256 + sc * 8]) = gA[i];
        *reinterpret_cast<uint4*>(&sW[r * 256 + sc * 8]) = gW[i];
    }
    __syncthreads();
    int lane = t & 31, warp = t >> 5;
    int m0 = warp * 16;
    float acc[8][4];
#pragma unroll
    for (int i = 0; i < 8; i++)
#pragma unroll
        for (int j = 0; j < 4; j++) acc[i][j] = 0.f;

    int arow = m0 + (lane & 7) + ((lane >> 3) & 1) * 8;
    int akc  = (lane >> 4);
    int brin = ((lane >> 4) & 1) * 8 + (lane & 7);
    int bkc  = (lane >> 3) & 1;
#pragma unroll
    for (int kt = 0; kt < 16; kt++) {
        int ac = kt * 2 + akc;
        uint32_t aaddr = su32(&sA[arow * 256 + ((ac ^ (arow & 7)) << 3)]);
        uint32_t a0, a1, a2, a3;
        asm volatile("ldmatrix.sync.aligned.m8n8.x4.shared.b16 {%0,%1,%2,%3}, [%4];"
            : "=r"(a0), "=r"(a1), "=r"(a2), "=r"(a3) : "r"(aaddr));
#pragma unroll
        for (int og = 0; og < 4; og++) {
            int brow = og * 16 + brin;
            int bc = kt * 2 + bkc;
            uint32_t baddr = su32(&sW[brow * 256 + ((bc ^ (brow & 7)) << 3)]);
            uint32_t b0, b1, b2, b3;
            // W2 is [o][k] row-major = K x N col-major: plain (no .trans) B fragment
            asm volatile("ldmatrix.sync.aligned.m8n8.x4.shared.b16 {%0,%1,%2,%3}, [%4];"
                : "=r"(b0), "=r"(b1), "=r"(b2), "=r"(b3) : "r"(baddr));
            MMA16816(acc[og * 2],     a0, a1, a2, a3, b0, b1);
            MMA16816(acc[og * 2 + 1], a0, a1, a2, a3, b2, b3);
        }
    }
    int r0 = base + m0 + (lane >> 2);
    int cq = lane & 3;
#pragma unroll
    for (int ot = 0; ot < 8; ot++) {
        g_h2h[r0 * 32 + ot * 4 + cq]       = __floats2half2_rn(acc[ot][0], acc[ot][1]);
        g_h2h[(r0 + 8) * 32 + ot * 4 + cq] = __floats2half2_rn(acc[ot][2], acc[ot][3]);
    }
    // ---- alpha2 epilogue: 2 threads per node over the sA tile ----
    {
        int n = t >> 1, half = t & 1;
        const __half2* sa2 = reinterpret_cast<const __half2*>(sA);
        float a = 0.f, b = 0.f;
        int kk0 = half * 64;
#pragma unroll 8
        for (int kk = kk0; kk < kk0 + 64; kk++) {
            int c = kk >> 2, w2 = kk & 3;
            float2 v = __half22float2(sa2[n * 128 + ((c ^ (n & 7)) << 2) + w2]);
            a += v.x * svs[2 * kk] + v.y * svs[2 * kk + 1];
            b += v.x * svd[2 * kk] + v.y * svd[2 * kk + 1];
        }
        a += __shfl_xor_sync(FULLM, a, 1);
        b += __shfl_xor_sync(FULLM, b, 1);
        if (half == 0 && base + n < NN) { g_as2[base + n] = a; g_ad2[base + n] = b; }
    }
}

// ---------------- layer 2 FUSED softmax + aggregate + FINAL projection -------------
__global__ void k_fagg2(const float* __restrict__ b2,
                        const float* __restrict__ fw, const float* __restrict__ fb,
                        float* __restrict__ out) {
    __shared__ float sw[8][CH2];
    __shared__ int   si[8][CH2];
    int wid = threadIdx.x >> 5, lane = threadIdx.x & 31;
    int d = blockIdx.x * 8 + wid;
    int beg = g_off[d], end = g_off[d + 1];
    int deg = end - beg;
    float ad = g_ad2[d];
    float ax = 0.f, ay = 0.f, gsv;
    if (deg <= 32) {
        int s = 0; float lg = NEG_INF;
        if (lane < deg) {
            s = g_eid[beg + lane];
            lg = lrelu(g_as2[s] + ad);
        }
        float m = lg;
#pragma unroll
        for (int o = 16; o > 0; o >>= 1) m = fmaxf(m, __shfl_xor_sync(FULLM, m, o));
        float w = (lane < deg) ? __expf(lg - m) : 0.f;
        float ss = w;
#pragma unroll
        for (int o = 16; o > 0; o >>= 1) ss += __shfl_xor_sync(FULLM, ss, o);
        float ax1 = 0.f, ay1 = 0.f;
        int e = 0;
        for (; e + 4 <= deg; e += 4) {
            float w0 = __shfl_sync(FULLM, w, e),     w1 = __shfl_sync(FULLM, w, e + 1);
            float w2 = __shfl_sync(FULLM, w, e + 2), w3 = __shfl_sync(FULLM, w, e + 3);
            int   s0 = __shfl_sync(FULLM, s, e),     s1 = __shfl_sync(FULLM, s, e + 1);
            int   s2 = __shfl_sync(FULLM, s, e + 2), s3 = __shfl_sync(FULLM, s, e + 3);
            float2 v0 = __half22float2(g_h2h[s0 * 32 + lane]);
            float2 v1 = __half22float2(g_h2h[s1 * 32 + lane]);
            float2 v2 = __half22float2(g_h2h[s2 * 32 + lane]);
            float2 v3 = __half22float2(g_h2h[s3 * 32 + lane]);
            ax  += w0 * v0.x + w2 * v2.x;  ay  += w0 * v0.y + w2 * v2.y;
            ax1 += w1 * v1.x + w3 * v3.x;  ay1 += w1 * v1.y + w3 * v3.y;
        }
        for (; e < deg; e++) {
            float we = __shfl_sync(FULLM, w, e);
            int   se = __shfl_sync(FULLM, s, e);
            float2 v = __half22float2(g_h2h[se * 32 + lane]);
            ax += we * v.x; ay += we * v.y;
        }
        ax += ax1; ay += ay1;
        gsv = ss;
    } else {
        float gmv = NEG_INF; gsv = 0.f;
        for (int cb = beg; cb < end; cb += CH2) {
            int cnt = min(end - cb, CH2);
            float m = NEG_INF;
            for (int e = lane; e < cnt; e += 32) {
                int s = g_eid[cb + e];
                si[wid][e] = s;
                float lg = lrelu(g_as2[s] + ad);
                sw[wid][e] = lg;
                m = fmaxf(m, lg);
            }
#pragma unroll
            for (int o = 16; o > 0; o >>= 1) m = fmaxf(m, __shfl_xor_sync(FULLM, m, o));
            float ssum = 0.f;
            for (int e = lane; e < cnt; e += 32) {
                float w = __expf(sw[wid][e] - m);
                sw[wid][e] = w;
                ssum += w;
            }
#pragma unroll
            for (int o = 16; o > 0; o >>= 1) ssum += __shfl_xor_sync(FULLM, ssum, o);
            __syncwarp();
            float cax = 0.f, cay = 0.f, cax1 = 0.f, cay1 = 0.f;
            const float* swh = sw[wid];
            const int* sih = si[wid];
            int e = 0;
            for (; e + 4 <= cnt; e += 4) {
                int i0 = sih[e], i1 = sih[e + 1], i2 = sih[e + 2], i3 = sih[e + 3];
                float w0 = swh[e], w1 = swh[e + 1], w2 = swh[e + 2], w3 = swh[e + 3];
                float2 v0 = __half22float2(g_h2h[i0 * 32 + lane]);
                float2 v1 = __half22float2(g_h2h[i1 * 32 + lane]);
                float2 v2 = __half22float2(g_h2h[i2 * 32 + lane]);
                float2 v3 = __half22float2(g_h2h[i3 * 32 + lane]);
                cax  += w0 * v0.x + w2 * v2.x;  cay  += w0 * v0.y + w2 * v2.y;
                cax1 += w1 * v1.x + w3 * v3.x;  cay1 += w1 * v1.y + w3 * v3.y;
            }
            for (; e < cnt; e++) {
                float w = swh[e];
                float2 v = __half22float2(g_h2h[sih[e] * 32 + lane]);
                cax += w * v.x; cay += w * v.y;
            }
            cax += cax1; cay += cay1;
            float nm = fmaxf(gmv, m);
            float f = __expf(gmv - nm), c = __expf(m - nm);
            gsv = gsv * f + ssum * c;
            ax = ax * f + cax * c;
            ay = ay * f + cay * c;
            gmv = nm;
            __syncwarp();
        }
    }
    float inv = 1.f / (gsv + 1e-16f);
    float2 bb = reinterpret_cast<const float2*>(b2)[lane];
    float ox = elu(ax * inv + bb.x);
    float oy = elu(ay * inv + bb.y);
    // fused final projection: out[d] = sum_c o2[c]*fw[c] + fb
    float2 fwv = reinterpret_cast<const float2*>(fw)[lane];
    float v = ox * fwv.x + oy * fwv.y;
#pragma unroll
    for (int o = 16; o > 0; o >>= 1) v += __shfl_xor_sync(FULLM, v, o);
    if (lane == 0) out[d] = v + fb[0];
}

// ---------------- launch --------------------------------------------------------------
extern "C" void kernel_launch(void* const* d_in, const int* in_sizes, int n_in,
                              void* d_out, int out_size) {
    const float* x   = (const float*)d_in[0];
    const int*   ei  = (const int*)d_in[1];
    const float* W1  = (const float*)d_in[2];
    const float* as1 = (const float*)d_in[3];
    const float* ad1 = (const float*)d_in[4];
    const float* b1  = (const float*)d_in[5];
    const float* W2  = (const float*)d_in[6];
    const float* as2 = (const float*)d_in[7];
    const float* ad2 = (const float*)d_in[8];
    const float* b2  = (const float*)d_in[9];
    const float* fw  = (const float*)d_in[10];
    const float* fb  = (const float*)d_in[11];
    float*       out = (float*)d_out;

    k_init2<<<2, 256>>>(ei, W1, as1, ad1, W2, as2, ad2);
    k_pre<<<(ET + 255) / 256, 256>>>(x, ei);
    k_scanF<<<NPART, 256>>>();
    k_scatter<<<(ET + 255) / 256, 256>>>(ei);
    k_fagg1g<<<NN / 8, 256>>>(x, W1, b1);
    k_gemm2<<<NN2 / 64, 128>>>();
    k_fagg2<<<NN / 8, 256>>>(b2, fw, fb, out);
}

// round 17
// speedup vs baseline: 1.0686x; 1.0686x over previous
#include <cuda_runtime.h>
#include <cuda_fp16.h>
#include <stdint.h>
#include <math.h>

#define NN 50000
#define NN2 50048          // padded to multiple of 64 for gemm2 tiles
#define FE 800000
#define ET (FE + NN)
#define NPART 196          // ceil(NN/256)
#define CH2 256
#define FULLM 0xffffffffu

// ---------------- scratch ----------------------------------------------------
__device__ __half2 g_o1h[NN2 * 128];   // elu(layer1 out) fp16 (gemm2 A)
__device__ float   g_as1[NN * 4];
__device__ float   g_ad1[NN * 4];
__device__ __half  g_W2h[64 * 256];    // W2 fp16
__device__ __half2 g_h2h[NN2 * 32];    // layer2 pre-agg features fp16
__device__ float   g_as2[NN];
__device__ float   g_ad2[NN];
__device__ int     g_eid[ET];
__device__ int     g_cnt[NN];
__device__ int     g_off[NN + 1];
__device__ int     g_cur[NN];
__device__ int     g_part[NPART];
__device__ int     g_is64;
__device__ float   g_ws1s[64];
__device__ float   g_ws1d[64];
__device__ float   g_v2s[256];
__device__ float   g_v2d[256];

__device__ __forceinline__ float lrelu(float v) { return v > 0.f ? v : 0.2f * v; }
__device__ __forceinline__ float elu(float v)   { return v > 0.f ? v : expm1f(v); }
__device__ __forceinline__ uint32_t su32(const void* p) {
    return (uint32_t)__cvta_generic_to_shared(p);
}
#define NEG_INF __int_as_float(0xff800000)

// ---------------- setup: zero counters + dtype detect + weight folds ------------
__global__ void k_setup(const int* __restrict__ ei32,
                        const float* __restrict__ W1,
                        const float* __restrict__ as1, const float* __restrict__ ad1,
                        const float* __restrict__ W2,
                        const float* __restrict__ as2, const float* __restrict__ ad2) {
    int t = threadIdx.x;
    int i = blockIdx.x * blockDim.x + t;
    if (i < NN) g_cnt[i] = 0;
    if (blockIdx.x == 0) {
        int nz = 0;
        for (int k = t; k < 1024; k += 256) nz |= ei32[2 * k + 1];
        int any = __syncthreads_or(nz);
        if (t == 0) g_is64 = (any == 0);
    } else if (blockIdx.x == 1) {
        if (t < 64) {
            int h = t >> 4, ii = t & 15;
            float s = 0.f, d = 0.f;
            for (int c = 0; c < 64; c++) {
                float w = W1[(h * 64 + c) * 16 + ii];
                s += as1[h * 64 + c] * w;
                d += ad1[h * 64 + c] * w;
            }
            g_ws1s[t] = s; g_ws1d[t] = d;
        }
        {
            float s = 0.f, d = 0.f;
            for (int o = 0; o < 64; o++) {
                float w = W2[o * 256 + t];
                s += as2[o] * w;
                d += ad2[o] * w;
            }
            g_v2s[t] = s; g_v2d[t] = d;
        }
        for (int j = 0; j < 64; j++) {
            int idx = j * 256 + t;
            g_W2h[idx] = __float2half(W2[idx]);
        }
    }
}

// ---------------- pre: layer-1 logits from x + edge in-degree counting -----------
__global__ void k_pre(const float* __restrict__ x, const int* __restrict__ ei32) {
    __shared__ float ws[64], wd[64];
    int t = threadIdx.x;
    if (t < 64) { ws[t] = g_ws1s[t]; wd[t] = g_ws1d[t]; }
    __syncthreads();
    int i = blockIdx.x * 256 + t;
    if (i < ET) {
        int d;
        if (i < FE) d = g_is64 ? ei32[2 * (FE + i)] : ei32[FE + i];
        else        d = i - FE;
        atomicAdd(&g_cnt[d], 1);
    }
    if (i < NN) {
        const float4* xv = reinterpret_cast<const float4*>(x + i * 16);
        float4 x0 = xv[0], x1 = xv[1], x2 = xv[2], x3 = xv[3];
        float4 av, bv;
        float* ap = (float*)&av;
        float* bp = (float*)&bv;
#pragma unroll
        for (int h = 0; h < 4; h++) {
            const float* s = ws + h * 16;
            const float* d = wd + h * 16;
            ap[h] = x0.x * s[0] + x0.y * s[1] + x0.z * s[2] + x0.w * s[3]
                  + x1.x * s[4] + x1.y * s[5] + x1.z * s[6] + x1.w * s[7]
                  + x2.x * s[8] + x2.y * s[9] + x2.z * s[10] + x2.w * s[11]
                  + x3.x * s[12] + x3.y * s[13] + x3.z * s[14] + x3.w * s[15];
            bp[h] = x0.x * d[0] + x0.y * d[1] + x0.z * d[2] + x0.w * d[3]
                  + x1.x * d[4] + x1.y * d[5] + x1.z * d[6] + x1.w * d[7]
                  + x2.x * d[8] + x2.y * d[9] + x2.z * d[10] + x2.w * d[11]
                  + x3.x * d[12] + x3.y * d[13] + x3.z * d[14] + x3.w * d[15];
        }
        *reinterpret_cast<float4*>(&g_as1[i * 4]) = av;
        *reinterpret_cast<float4*>(&g_ad1[i * 4]) = bv;
    }
}

// ---------------- scan part: per-256-block sums -----------------------------------
__global__ void k_scan_part() {
    __shared__ int sm[256];
    int b = blockIdx.x, t = threadIdx.x, i = b * 256 + t;
    sm[t] = (i < NN) ? g_cnt[i] : 0;
    __syncthreads();
#pragma unroll
    for (int s = 128; s > 0; s >>= 1) { if (t < s) sm[t] += sm[t + s]; __syncthreads(); }
    if (t == 0) g_part[b] = sm[0];
}
// ---------------- scan finish: redundant partial-scan + local scan ----------------
__global__ void k_scan_fin2() {
    __shared__ int sp[256];
    __shared__ int sm[256];
    int b = blockIdx.x, t = threadIdx.x, i = b * 256 + t;
    sp[t] = (t < NPART) ? g_part[t] : 0;
    int v = (i < NN) ? g_cnt[i] : 0;
    sm[t] = v;
    __syncthreads();
#pragma unroll
    for (int s = 1; s < 256; s <<= 1) {
        int a = (t >= s) ? sp[t - s] : 0;
        int c = (t >= s) ? sm[t - s] : 0;
        __syncthreads();
        sp[t] += a; sm[t] += c;
        __syncthreads();
    }
    int base = (b > 0) ? sp[b - 1] : 0;      // exclusive prefix of parts
    if (i < NN) {
        int off = base + sm[t] - v;
        g_off[i] = off; g_cur[i] = off;
    }
    if (b == 0 && t == 0) g_off[NN] = ET;
}
// ---------------- scatter: 2 edges per thread (MLP 2, latency-bound kernel) -------
__global__ void k_scatter(const int* __restrict__ ei32) {
    int base = (blockIdx.x * blockDim.x + threadIdx.x) * 2;
#pragma unroll
    for (int k = 0; k < 2; k++) {
        int i = base + k;
        if (i >= ET) return;
        int s, d;
        if (i < FE) {
            if (g_is64) { s = ei32[2 * i]; d = ei32[2 * (FE + i)]; }
            else        { s = ei32[i];     d = ei32[FE + i]; }
        } else { s = i - FE; d = s; }
        int pos = atomicAdd(&g_cur[d], 1);
        g_eid[pos] = s;
    }
}

// ---------------- layer 1 FUSED: x-aggregation (linearity) + GEMM + ELU -----------
// Phase A (warp per dst, 8 dst/block): xagg[d][h][:] = softmax-weighted sum of x rows,
//   staged in SMEM. Phase B: out1 = xagg @ W1^T + b1 -> ELU -> fp16 o1h.
__global__ void k_fagg1g(const float* __restrict__ x,
                         const float* __restrict__ W1, const float* __restrict__ b1) {
    __shared__ float xs[8 * 64];
    int t = threadIdx.x;
    int wid = t >> 5, lane = t & 31;
    int b = blockIdx.x;
    int d = b * 8 + wid;
    {
        int beg = g_off[d], end = g_off[d + 1];
        float4 adv = *reinterpret_cast<const float4*>(&g_ad1[d * 4]);
        int c = lane & 15, half = lane >> 4;
        float gm0 = NEG_INF, gm1 = NEG_INF, gm2 = NEG_INF, gm3 = NEG_INF;
        float gs0 = 0.f, gs1 = 0.f, gs2 = 0.f, gs3 = 0.f;
        float a0 = 0.f, a1 = 0.f, a2 = 0.f, a3 = 0.f;
        for (int cb = beg; cb < end; cb += 32) {
            int cnt = min(end - cb, 32);
            int s = 0;
            float l0 = NEG_INF, l1 = NEG_INF, l2 = NEG_INF, l3 = NEG_INF;
            if (lane < cnt) {
                s = g_eid[cb + lane];
                float4 as = *reinterpret_cast<const float4*>(&g_as1[s * 4]);
                l0 = lrelu(as.x + adv.x); l1 = lrelu(as.y + adv.y);
                l2 = lrelu(as.z + adv.z); l3 = lrelu(as.w + adv.w);
            }
            float m0 = l0, m1 = l1, m2 = l2, m3 = l3;
#pragma unroll
            for (int o = 16; o > 0; o >>= 1) {
                m0 = fmaxf(m0, __shfl_xor_sync(FULLM, m0, o));
                m1 = fmaxf(m1, __shfl_xor_sync(FULLM, m1, o));
                m2 = fmaxf(m2, __shfl_xor_sync(FULLM, m2, o));
                m3 = fmaxf(m3, __shfl_xor_sync(FULLM, m3, o));
            }
            float w0 = (lane < cnt) ? __expf(l0 - m0) : 0.f;
            float w1 = (lane < cnt) ? __expf(l1 - m1) : 0.f;
            float w2 = (lane < cnt) ? __expf(l2 - m2) : 0.f;
            float w3 = (lane < cnt) ? __expf(l3 - m3) : 0.f;
            float s0 = w0, s1 = w1, s2 = w2, s3 = w3;
#pragma unroll
            for (int o = 16; o > 0; o >>= 1) {
                s0 += __shfl_xor_sync(FULLM, s0, o);
                s1 += __shfl_xor_sync(FULLM, s1, o);
                s2 += __shfl_xor_sync(FULLM, s2, o);
                s3 += __shfl_xor_sync(FULLM, s3, o);
            }
            // gather x rows: two 16-lane halves each own alternating edges
            float c0 = 0.f, c1 = 0.f, c2 = 0.f, c3 = 0.f;
            for (int eb = 0; eb < cnt; eb += 2) {           // uniform trip count
                int e = (eb + half) & 31;
                float we0 = __shfl_sync(FULLM, w0, e);
                float we1 = __shfl_sync(FULLM, w1, e);
                float we2 = __shfl_sync(FULLM, w2, e);
                float we3 = __shfl_sync(FULLM, w3, e);
                int   se  = __shfl_sync(FULLM, s,  e);
                if (eb + half < cnt) {
                    float xv = x[se * 16 + c];
                    c0 += we0 * xv; c1 += we1 * xv;
                    c2 += we2 * xv; c3 += we3 * xv;
                }
            }
            float nm0 = fmaxf(gm0, m0), nm1 = fmaxf(gm1, m1);
            float nm2 = fmaxf(gm2, m2), nm3 = fmaxf(gm3, m3);
            float f0 = __expf(gm0 - nm0), q0 = __expf(m0 - nm0);
            float f1 = __expf(gm1 - nm1), q1 = __expf(m1 - nm1);
            float f2 = __expf(gm2 - nm2), q2 = __expf(m2 - nm2);
            float f3 = __expf(gm3 - nm3), q3 = __expf(m3 - nm3);
            gs0 = gs0 * f0 + s0 * q0;  a0 = a0 * f0 + c0 * q0;  gm0 = nm0;
            gs1 = gs1 * f1 + s1 * q1;  a1 = a1 * f1 + c1 * q1;  gm1 = nm1;
            gs2 = gs2 * f2 + s2 * q2;  a2 = a2 * f2 + c2 * q2;  gm2 = nm2;
            gs3 = gs3 * f3 + s3 * q3;  a3 = a3 * f3 + c3 * q3;  gm3 = nm3;
        }
        a0 += __shfl_down_sync(FULLM, a0, 16);
        a1 += __shfl_down_sync(FULLM, a1, 16);
        a2 += __shfl_down_sync(FULLM, a2, 16);
        a3 += __shfl_down_sync(FULLM, a3, 16);
        if (lane < 16) {
            float* o = xs + wid * 64;
            o[c]      = a0 / (gs0 + 1e-16f);
            o[16 + c] = a1 / (gs1 + 1e-16f);
            o[32 + c] = a2 / (gs2 + 1e-16f);
            o[48 + c] = a3 / (gs3 + 1e-16f);
        }
    }
    __syncthreads();
    // ---- phase B: out1 = xagg @ W1^T + b1 -> ELU -> fp16 ----
    const float4* W4 = reinterpret_cast<const float4*>(W1) + t * 4;
    float4 w0 = W4[0], w1 = W4[1], w2 = W4[2], w3 = W4[3];
    float bb = b1[t];
    int h16 = (t >> 6) * 16;
#pragma unroll
    for (int j = 0; j < 8; j++) {
        const float* xv = xs + j * 64 + h16;
        float acc = xv[0] * w0.x + xv[1] * w0.y + xv[2] * w0.z + xv[3] * w0.w
                  + xv[4] * w1.x + xv[5] * w1.y + xv[6] * w1.z + xv[7] * w1.w
                  + xv[8] * w2.x + xv[9] * w2.y + xv[10] * w2.z + xv[11] * w2.w
                  + xv[12] * w3.x + xv[13] * w3.y + xv[14] * w3.z + xv[15] * w3.w;
        acc = elu(acc + bb);
        float hi = __shfl_down_sync(FULLM, acc, 1);
        if (!(t & 1)) g_o1h[(b * 8 + j) * 128 + (t >> 1)] = __floats2half2_rn(acc, hi);
    }
}

// ---------------- layer 2 GEMM (tensor cores) + fused alpha2 epilogue -------------
#define MMA16816(C, A0, A1, A2, A3, B0, B1)                                   \
    asm volatile("mma.sync.aligned.m16n8k16.row.col.f32.f16.f16.f32 "          \
        "{%0,%1,%2,%3}, {%4,%5,%6,%7}, {%8,%9}, {%0,%1,%2,%3};"                \
        : "+f"(C[0]), "+f"(C[1]), "+f"(C[2]), "+f"(C[3])                       \
        : "r"(A0), "r"(A1), "r"(A2), "r"(A3), "r"(B0), "r"(B1))

__global__ void k_gemm2() {
    __shared__ __align__(16) __half sA[64 * 256];
    __shared__ __align__(16) __half sW[64 * 256];
    __shared__ float svs[256], svd[256];
    int t = threadIdx.x;               // 128
    int base = blockIdx.x * 64;
    const uint4* gA = reinterpret_cast<const uint4*>(g_o1h) + base * 32;
    const uint4* gW = reinterpret_cast<const uint4*>(g_W2h);
    svs[t] = g_v2s[t]; svs[t + 128] = g_v2s[t + 128];
    svd[t] = g_v2d[t]; svd[t + 128] = g_v2d[t + 128];
#pragma unroll
    for (int j = 0; j < 16; j++) {
        int i = j * 128 + t;
        int r = i >> 5, c = i & 31;
        int sc = c ^ (r & 7);
        *reinterpret_cast<uint4*>(&sA[r * 256 + sc * 8]) = gA[i];
        *reinterpret_cast<uint4*>(&sW[r * 256 + sc * 8]) = gW[i];
    }
    __syncthreads();
    int lane = t & 31, warp = t >> 5;
    int m0 = warp * 16;
    float acc[8][4];
#pragma unroll
    for (int i = 0; i < 8; i++)
#pragma unroll
        for (int j = 0; j < 4; j++) acc[i][j] = 0.f;

    int arow = m0 + (lane & 7) + ((lane >> 3) & 1) * 8;
    int akc  = (lane >> 4);
    int brin = ((lane >> 4) & 1) * 8 + (lane & 7);
    int bkc  = (lane >> 3) & 1;
#pragma unroll
    for (int kt = 0; kt < 16; kt++) {
        int ac = kt * 2 + akc;
        uint32_t aaddr = su32(&sA[arow * 256 + ((ac ^ (arow & 7)) << 3)]);
        uint32_t a0, a1, a2, a3;
        asm volatile("ldmatrix.sync.aligned.m8n8.x4.shared.b16 {%0,%1,%2,%3}, [%4];"
            : "=r"(a0), "=r"(a1), "=r"(a2), "=r"(a3) : "r"(aaddr));
#pragma unroll
        for (int og = 0; og < 4; og++) {
            int brow = og * 16 + brin;
            int bc = kt * 2 + bkc;
            uint32_t baddr = su32(&sW[brow * 256 + ((bc ^ (brow & 7)) << 3)]);
            uint32_t b0, b1, b2, b3;
            // W2 is [o][k] row-major = K x N col-major: plain (no .trans) B fragment
            asm volatile("ldmatrix.sync.aligned.m8n8.x4.shared.b16 {%0,%1,%2,%3}, [%4];"
                : "=r"(b0), "=r"(b1), "=r"(b2), "=r"(b3) : "r"(baddr));
            MMA16816(acc[og * 2],     a0, a1, a2, a3, b0, b1);
            MMA16816(acc[og * 2 + 1], a0, a1, a2, a3, b2, b3);
        }
    }
    int r0 = base + m0 + (lane >> 2);
    int cq = lane & 3;
#pragma unroll
    for (int ot = 0; ot < 8; ot++) {
        g_h2h[r0 * 32 + ot * 4 + cq]       = __floats2half2_rn(acc[ot][0], acc[ot][1]);
        g_h2h[(r0 + 8) * 32 + ot * 4 + cq] = __floats2half2_rn(acc[ot][2], acc[ot][3]);
    }
    // ---- alpha2 epilogue: 2 threads per node over the sA tile ----
    {
        int n = t >> 1, half = t & 1;
        const __half2* sa2 = reinterpret_cast<const __half2*>(sA);
        float a = 0.f, b = 0.f;
        int kk0 = half * 64;
#pragma unroll 8
        for (int kk = kk0; kk < kk0 + 64; kk++) {
            int c = kk >> 2, w2 = kk & 3;
            float2 v = __half22float2(sa2[n * 128 + ((c ^ (n & 7)) << 2) + w2]);
            a += v.x * svs[2 * kk] + v.y * svs[2 * kk + 1];
            b += v.x * svd[2 * kk] + v.y * svd[2 * kk + 1];
        }
        a += __shfl_xor_sync(FULLM, a, 1);
        b += __shfl_xor_sync(FULLM, b, 1);
        if (half == 0 && base + n < NN) { g_as2[base + n] = a; g_ad2[base + n] = b; }
    }
}

// ---------------- layer 2 FUSED softmax + aggregate + FINAL projection -------------
__global__ void k_fagg2(const float* __restrict__ b2,
                        const float* __restrict__ fw, const float* __restrict__ fb,
                        float* __restrict__ out) {
    __shared__ float sw[8][CH2];
    __shared__ int   si[8][CH2];
    int wid = threadIdx.x >> 5, lane = threadIdx.x & 31;
    int d = blockIdx.x * 8 + wid;
    int beg = g_off[d], end = g_off[d + 1];
    int deg = end - beg;
    float ad = g_ad2[d];
    float ax = 0.f, ay = 0.f, gsv;
    if (deg <= 32) {
        int s = 0; float lg = NEG_INF;
        if (lane < deg) {
            s = g_eid[beg + lane];
            lg = lrelu(g_as2[s] + ad);
        }
        float m = lg;
#pragma unroll
        for (int o = 16; o > 0; o >>= 1) m = fmaxf(m, __shfl_xor_sync(FULLM, m, o));
        float w = (lane < deg) ? __expf(lg - m) : 0.f;
        float ss = w;
#pragma unroll
        for (int o = 16; o > 0; o >>= 1) ss += __shfl_xor_sync(FULLM, ss, o);
        float ax1 = 0.f, ay1 = 0.f;
        int e = 0;
        for (; e + 4 <= deg; e += 4) {
            float w0 = __shfl_sync(FULLM, w, e),     w1 = __shfl_sync(FULLM, w, e + 1);
            float w2 = __shfl_sync(FULLM, w, e + 2), w3 = __shfl_sync(FULLM, w, e + 3);
            int   s0 = __shfl_sync(FULLM, s, e),     s1 = __shfl_sync(FULLM, s, e + 1);
            int   s2 = __shfl_sync(FULLM, s, e + 2), s3 = __shfl_sync(FULLM, s, e + 3);
            float2 v0 = __half22float2(g_h2h[s0 * 32 + lane]);
            float2 v1 = __half22float2(g_h2h[s1 * 32 + lane]);
            float2 v2 = __half22float2(g_h2h[s2 * 32 + lane]);
            float2 v3 = __half22float2(g_h2h[s3 * 32 + lane]);
            ax  += w0 * v0.x + w2 * v2.x;  ay  += w0 * v0.y + w2 * v2.y;
            ax1 += w1 * v1.x + w3 * v3.x;  ay1 += w1 * v1.y + w3 * v3.y;
        }
        for (; e < deg; e++) {
            float we = __shfl_sync(FULLM, w, e);
            int   se = __shfl_sync(FULLM, s, e);
            float2 v = __half22float2(g_h2h[se * 32 + lane]);
            ax += we * v.x; ay += we * v.y;
        }
        ax += ax1; ay += ay1;
        gsv = ss;
    } else {
        float gmv = NEG_INF; gsv = 0.f;
        for (int cb = beg; cb < end; cb += CH2) {
            int cnt = min(end - cb, CH2);
            float m = NEG_INF;
            for (int e = lane; e < cnt; e += 32) {
                int s = g_eid[cb + e];
                si[wid][e] = s;
                float lg = lrelu(g_as2[s] + ad);
                sw[wid][e] = lg;
                m = fmaxf(m, lg);
            }
#pragma unroll
            for (int o = 16; o > 0; o >>= 1) m = fmaxf(m, __shfl_xor_sync(FULLM, m, o));
            float ssum = 0.f;
            for (int e = lane; e < cnt; e += 32) {
                float w = __expf(sw[wid][e] - m);
                sw[wid][e] = w;
                ssum += w;
            }
#pragma unroll
            for (int o = 16; o > 0; o >>= 1) ssum += __shfl_xor_sync(FULLM, ssum, o);
            __syncwarp();
            float cax = 0.f, cay = 0.f, cax1 = 0.f, cay1 = 0.f;
            const float* swh = sw[wid];
            const int* sih = si[wid];
            int e = 0;
            for (; e + 4 <= cnt; e += 4) {
                int i0 = sih[e], i1 = sih[e + 1], i2 = sih[e + 2], i3 = sih[e + 3];
                float w0 = swh[e], w1 = swh[e + 1], w2 = swh[e + 2], w3 = swh[e + 3];
                float2 v0 = __half22float2(g_h2h[i0 * 32 + lane]);
                float2 v1 = __half22float2(g_h2h[i1 * 32 + lane]);
                float2 v2 = __half22float2(g_h2h[i2 * 32 + lane]);
                float2 v3 = __half22float2(g_h2h[i3 * 32 + lane]);
                cax  += w0 * v0.x + w2 * v2.x;  cay  += w0 * v0.y + w2 * v2.y;
                cax1 += w1 * v1.x + w3 * v3.x;  cay1 += w1 * v1.y + w3 * v3.y;
            }
            for (; e < cnt; e++) {
                float w = swh[e];
                float2 v = __half22float2(g_h2h[sih[e] * 32 + lane]);
                cax += w * v.x; cay += w * v.y;
            }
            cax += cax1; cay += cay1;
            float nm = fmaxf(gmv, m);
            float f = __expf(gmv - nm), c = __expf(m - nm);
            gsv = gsv * f + ssum * c;
            ax = ax * f + cax * c;
            ay = ay * f + cay * c;
            gmv = nm;
            __syncwarp();
        }
    }
    float inv = 1.f / (gsv + 1e-16f);
    float2 bb = reinterpret_cast<const float2*>(b2)[lane];
    float ox = elu(ax * inv + bb.x);
    float oy = elu(ay * inv + bb.y);
    // fused final projection: out[d] = sum_c o2[c]*fw[c] + fb
    float2 fwv = reinterpret_cast<const float2*>(fw)[lane];
    float v = ox * fwv.x + oy * fwv.y;
#pragma unroll
    for (int o = 16; o > 0; o >>= 1) v += __shfl_xor_sync(FULLM, v, o);
    if (lane == 0) out[d] = v + fb[0];
}

// ---------------- launch --------------------------------------------------------------
extern "C" void kernel_launch(void* const* d_in, const int* in_sizes, int n_in,
                              void* d_out, int out_size) {
    const float* x   = (const float*)d_in[0];
    const int*   ei  = (const int*)d_in[1];
    const float* W1  = (const float*)d_in[2];
    const float* as1 = (const float*)d_in[3];
    const float* ad1 = (const float*)d_in[4];
    const float* b1  = (const float*)d_in[5];
    const float* W2  = (const float*)d_in[6];
    const float* as2 = (const float*)d_in[7];
    const float* ad2 = (const float*)d_in[8];
    const float* b2  = (const float*)d_in[9];
    const float* fw  = (const float*)d_in[10];
    const float* fb  = (const float*)d_in[11];
    float*       out = (float*)d_out;

    k_setup<<<NPART, 256>>>(ei, W1, as1, ad1, W2, as2, ad2);
    k_pre<<<(ET + 255) / 256, 256>>>(x, ei);
    k_scan_part<<<NPART, 256>>>();
    k_scan_fin2<<<NPART, 256>>>();
    k_scatter<<<(ET / 2 + 255) / 256, 256>>>(ei);
    k_fagg1g<<<NN / 8, 256>>>(x, W1, b1);
    k_gemm2<<<NN2 / 64, 128>>>();
    k_fagg2<<<NN / 8, 256>>>(b2, fw, fb, out);
}